// round 3
// baseline (speedup 1.0000x reference)
#include <cuda_runtime.h>
#include <cuda_bf16.h>
#include <cstdint>

// ---------------------------------------------------------------------------
// GraphSAGE (3x SAGEConv mean-aggr + ReLU + dropout) on GB300.
//
// Structure per layer:  h' = act( mean_scatter(h)[dst] @ wl^T + bl + h @ wr^T )
// Linearity trick for layer 2 (D_H=128 -> D_OUT=64): transform FIRST, then
// scatter 64 dims instead of 128 (halves the dominant L2 atomic traffic).
// ---------------------------------------------------------------------------

constexpr int   NN   = 50000;     // nodes
constexpr int   EE   = 800000;    // edges
constexpr int   D    = 128;       // D_IN == D_H
constexpr int   DO   = 64;        // D_OUT
constexpr float PDROP = 0.3f;
constexpr float INV_KEEP = 1.0f / 0.7f;

// ---- scratch (static device globals; no allocation allowed) ----
__device__ __align__(256) float g_agg[NN * D];     // scatter-sum buffer (reused, 64-d uses prefix)
__device__ __align__(256) float g_h0 [NN * D];
__device__ __align__(256) float g_h1 [NN * D];
__device__ __align__(256) float g_y  [NN * DO];    // h1 @ wl2^T (pre-aggregation transform)
__device__ __align__(256) float g_cnt[NN];
__device__ __align__(256) float g_inv[NN];
__device__ __align__(256) float g_wT [5 * D * D];  // wl0T, wr0T, wl1T, wr1T, [wl2T|wr2T]

// ---------------------------------------------------------------------------
// Prep: transpose weights to [k][n] layout so GEMM W loads are coalesced.
// Segment 4 packs wl2 (cols 0..63) and wr2 (cols 64..127) side by side.
// ---------------------------------------------------------------------------
__global__ void prep_weights(const float* __restrict__ wl0, const float* __restrict__ wr0,
                             const float* __restrict__ wl1, const float* __restrict__ wr1,
                             const float* __restrict__ wl2, const float* __restrict__ wr2) {
    int idx = blockIdx.x * blockDim.x + threadIdx.x;
    if (idx >= 5 * D * D) return;
    int seg = idx / (D * D);
    int r   = idx % (D * D);
    int k = r / D, n = r % D;
    float v;
    switch (seg) {
        case 0:  v = wl0[n * D + k]; break;
        case 1:  v = wr0[n * D + k]; break;
        case 2:  v = wl1[n * D + k]; break;
        case 3:  v = wr1[n * D + k]; break;
        default: v = (n < DO) ? wl2[n * D + k] : wr2[(n - DO) * D + k]; break;
    }
    g_wT[idx] = v;
}

__global__ void zero_kernel(float4* __restrict__ p, int n4) {
    int i = blockIdx.x * blockDim.x + threadIdx.x;
    if (i < n4) p[i] = make_float4(0.f, 0.f, 0.f, 0.f);
}

__global__ void count_kernel(const int* __restrict__ ei) {
    int e = blockIdx.x * blockDim.x + threadIdx.x;
    if (e < EE) atomicAdd(&g_cnt[ei[EE + e]], 1.0f);
}

__global__ void inv_kernel() {
    int i = blockIdx.x * blockDim.x + threadIdx.x;
    if (i < NN) g_inv[i] = 1.0f / fmaxf(g_cnt[i], 1.0f);
}

// ---------------------------------------------------------------------------
// Scatter-add: one edge row = NC float4 chunks. 32 threads/edge for 128-d,
// 16/edge for 64-d. Uses sm_90+ vector reduction (red.global.add.v4.f32):
// 4x fewer LTS atomic ops than scalar atomicAdd. Edge-index loads are
// warp-uniform (block=256 => 8 or 16 edges per block, lane groups aligned).
// ---------------------------------------------------------------------------
template <int NC>
__global__ void scatter_kernel(const float4* __restrict__ feat, float4* __restrict__ agg,
                               const int* __restrict__ ei) {
    int gid = blockIdx.x * blockDim.x + threadIdx.x;
    int e = gid / NC;
    int c = gid % NC;
    int s = __ldg(&ei[e]);
    int d = __ldg(&ei[EE + e]);
    float4 v = __ldg(&feat[(long)s * NC + c]);
    float4* dst = &agg[(long)d * NC + c];
    asm volatile("red.global.add.v4.f32 [%0], {%1,%2,%3,%4};"
                 :: "l"(dst), "f"(v.x), "f"(v.y), "f"(v.z), "f"(v.w)
                 : "memory");
}

// ---------------------------------------------------------------------------
// Fused GEMM.
// MODE 0 (layers 0/1): C = relu( (agg*inv) @ Wl^T + b + Aprev @ Wr^T ) * dropout
//   K = 256 split into two 128 segments (A1 scaled by inv, then A2).
// MODE 1 (layer 2):   cols 0..63  -> out1 (y = h1 @ wl2^T, no bias)
//                     cols 64..127-> out2 (r = h1 @ wr2^T + bl2) == d_out
// Tiling: BM=BN=128, BK=16, 256 threads, 8x8 accum per thread.
// ---------------------------------------------------------------------------
template <int MODE>
__launch_bounds__(256, 2)
__global__ void gemm_kernel(const float* __restrict__ A1, const float* __restrict__ A2,
                            const float* __restrict__ WT, const float* __restrict__ bias,
                            const float* __restrict__ inv, const float* __restrict__ u,
                            float* __restrict__ out1, float* __restrict__ out2) {
    constexpr int BM = 128, BN = 128, BK = 16;
    constexpr int KT = (MODE == 0) ? 256 : 128;
    __shared__ float As[BK][BM + 4];
    __shared__ float Ws[BK][BN];

    const int tid = threadIdx.x;
    const int tx = tid & 15;      // 0..15 -> 8 output cols each
    const int ty = tid >> 4;      // 0..15 -> 8 output rows each
    const int mBase = blockIdx.x * BM;

    float acc[8][8];
    #pragma unroll
    for (int i = 0; i < 8; ++i)
        #pragma unroll
        for (int j = 0; j < 8; ++j) acc[i][j] = 0.f;

    for (int kb = 0; kb < KT; kb += BK) {
        // ---- load A tile (transposed into As[k][m]) ----
        const float* A = A1;
        int ko = kb;
        bool sc = false;
        if constexpr (MODE == 0) {
            if (kb >= 128) { A = A2; ko = kb - 128; }
            else           { sc = true; }
        }
        #pragma unroll
        for (int it = 0; it < 2; ++it) {
            int j   = tid + it * 256;          // 0..511
            int row = j >> 2;                  // 0..127
            int kq  = (j & 3) * 4;             // 0,4,8,12
            int gr  = mBase + row;
            float4 v = make_float4(0.f, 0.f, 0.f, 0.f);
            if (gr < NN) {
                v = __ldg((const float4*)&A[(long)gr * D + ko + kq]);
                if constexpr (MODE == 0) {
                    if (sc) {
                        float s = __ldg(&inv[gr]);
                        v.x *= s; v.y *= s; v.z *= s; v.w *= s;
                    }
                }
            }
            As[kq + 0][row] = v.x;
            As[kq + 1][row] = v.y;
            As[kq + 2][row] = v.z;
            As[kq + 3][row] = v.w;
        }
        // ---- load W tile ----
        #pragma unroll
        for (int it = 0; it < 2; ++it) {
            int j  = tid + it * 256;
            int kr = j >> 5;                   // 0..15
            int nq = (j & 31) * 4;             // 0..124
            float4 w = __ldg((const float4*)&WT[(long)(kb + kr) * BN + nq]);
            *(float4*)&Ws[kr][nq] = w;
        }
        __syncthreads();

        #pragma unroll
        for (int kk = 0; kk < BK; ++kk) {
            float a[8], w[8];
            *(float4*)&a[0] = *(const float4*)&As[kk][ty * 8];
            *(float4*)&a[4] = *(const float4*)&As[kk][ty * 8 + 4];
            *(float4*)&w[0] = *(const float4*)&Ws[kk][tx * 8];
            *(float4*)&w[4] = *(const float4*)&Ws[kk][tx * 8 + 4];
            #pragma unroll
            for (int i = 0; i < 8; ++i)
                #pragma unroll
                for (int j = 0; j < 8; ++j)
                    acc[i][j] = fmaf(a[i], w[j], acc[i][j]);
        }
        __syncthreads();
    }

    // ---- epilogue ----
    if constexpr (MODE == 0) {
        float bs[8];
        #pragma unroll
        for (int j = 0; j < 8; ++j) bs[j] = __ldg(&bias[tx * 8 + j]);
        #pragma unroll
        for (int i = 0; i < 8; ++i) {
            int gr = mBase + ty * 8 + i;
            if (gr >= NN) continue;
            #pragma unroll
            for (int jc = 0; jc < 2; ++jc) {
                float4 uu = __ldg((const float4*)&u[(long)gr * D + tx * 8 + jc * 4]);
                float4 o;
                o.x = fmaxf(acc[i][jc * 4 + 0] + bs[jc * 4 + 0], 0.f) * ((uu.x >= PDROP) ? INV_KEEP : 0.f);
                o.y = fmaxf(acc[i][jc * 4 + 1] + bs[jc * 4 + 1], 0.f) * ((uu.y >= PDROP) ? INV_KEEP : 0.f);
                o.z = fmaxf(acc[i][jc * 4 + 2] + bs[jc * 4 + 2], 0.f) * ((uu.z >= PDROP) ? INV_KEEP : 0.f);
                o.w = fmaxf(acc[i][jc * 4 + 3] + bs[jc * 4 + 3], 0.f) * ((uu.w >= PDROP) ? INV_KEEP : 0.f);
                *(float4*)&out1[(long)gr * D + tx * 8 + jc * 4] = o;
            }
        }
    } else {
        float bs[8];
        #pragma unroll
        for (int j = 0; j < 8; ++j)
            bs[j] = (tx >= 8) ? __ldg(&bias[tx * 8 - 64 + j]) : 0.f;
        #pragma unroll
        for (int i = 0; i < 8; ++i) {
            int gr = mBase + ty * 8 + i;
            if (gr >= NN) continue;
            if (tx < 8) {                       // cols 0..63 -> y
                #pragma unroll
                for (int jc = 0; jc < 2; ++jc) {
                    float4 o = make_float4(acc[i][jc * 4 + 0], acc[i][jc * 4 + 1],
                                           acc[i][jc * 4 + 2], acc[i][jc * 4 + 3]);
                    *(float4*)&out1[(long)gr * DO + tx * 8 + jc * 4] = o;
                }
            } else {                            // cols 64..127 -> residual into d_out
                int nb = tx * 8 - 64;
                #pragma unroll
                for (int jc = 0; jc < 2; ++jc) {
                    float4 o = make_float4(acc[i][jc * 4 + 0] + bs[jc * 4 + 0],
                                           acc[i][jc * 4 + 1] + bs[jc * 4 + 1],
                                           acc[i][jc * 4 + 2] + bs[jc * 4 + 2],
                                           acc[i][jc * 4 + 3] + bs[jc * 4 + 3]);
                    *(float4*)&out2[(long)gr * DO + nb + jc * 4] = o;
                }
            }
        }
    }
}

// out[i] += agg64[i] * inv[node]   (final mean + add)
__global__ void finalize_kernel(float* __restrict__ out) {
    int i = blockIdx.x * blockDim.x + threadIdx.x;     // float4 index
    if (i < NN * DO / 4) {
        int node = i / (DO / 4);
        float s = g_inv[node];
        float4 a = ((const float4*)g_agg)[i];
        float4 o = ((float4*)out)[i];
        o.x += a.x * s; o.y += a.y * s; o.z += a.z * s; o.w += a.w * s;
        ((float4*)out)[i] = o;
    }
}

// ---------------------------------------------------------------------------
extern "C" void kernel_launch(void* const* d_in, const int* in_sizes, int n_in,
                              void* d_out, int out_size) {
    const float* x   = (const float*)d_in[0];
    const float* u1  = (const float*)d_in[1];
    const float* u2  = (const float*)d_in[2];
    const float* wl0 = (const float*)d_in[3];
    const float* bl0 = (const float*)d_in[4];
    const float* wr0 = (const float*)d_in[5];
    const float* wl1 = (const float*)d_in[6];
    const float* bl1 = (const float*)d_in[7];
    const float* wr1 = (const float*)d_in[8];
    const float* wl2 = (const float*)d_in[9];
    const float* bl2 = (const float*)d_in[10];
    const float* wr2 = (const float*)d_in[11];
    const int*   ei  = (const int*)d_in[12];
    float* out = (float*)d_out;

    float *agg, *h0, *h1, *y, *cnt, *inv, *wT;
    cudaGetSymbolAddress((void**)&agg, g_agg);
    cudaGetSymbolAddress((void**)&h0,  g_h0);
    cudaGetSymbolAddress((void**)&h1,  g_h1);
    cudaGetSymbolAddress((void**)&y,   g_y);
    cudaGetSymbolAddress((void**)&cnt, g_cnt);
    cudaGetSymbolAddress((void**)&inv, g_inv);
    cudaGetSymbolAddress((void**)&wT,  g_wT);

    const int gemmBlocks = (NN + 127) / 128;           // 391

    // prep: weight transposes + degree counts + inverse
    prep_weights<<<(5 * D * D + 255) / 256, 256>>>(wl0, wr0, wl1, wr1, wl2, wr2);
    zero_kernel<<<(NN / 4 + 255) / 256, 256>>>((float4*)cnt, NN / 4);
    count_kernel<<<EE / 256, 256>>>(ei);
    inv_kernel<<<(NN + 255) / 256, 256>>>();

    // ---- layer 0 ----
    zero_kernel<<<NN * D / 4 / 256, 256>>>((float4*)agg, NN * D / 4);
    scatter_kernel<32><<<EE * 32 / 256, 256>>>((const float4*)x, (float4*)agg, ei);
    gemm_kernel<0><<<gemmBlocks, 256>>>(agg, x, wT, bl0, inv, u1, h0, nullptr);

    // ---- layer 1 ----
    zero_kernel<<<NN * D / 4 / 256, 256>>>((float4*)agg, NN * D / 4);
    scatter_kernel<32><<<EE * 32 / 256, 256>>>((const float4*)h0, (float4*)agg, ei);
    gemm_kernel<0><<<gemmBlocks, 256>>>(agg, h0, wT + 2 * D * D, bl1, inv, u2, h1, nullptr);

    // ---- layer 2 (transform first, then 64-d scatter) ----
    gemm_kernel<1><<<gemmBlocks, 256>>>(h1, nullptr, wT + 4 * D * D, bl2, nullptr, nullptr, y, out);
    zero_kernel<<<NN * DO / 4 / 256, 256>>>((float4*)agg, NN * DO / 4);
    scatter_kernel<16><<<EE * 16 / 256, 256>>>((const float4*)y, (float4*)agg, ei);
    finalize_kernel<<<(NN * DO / 4 + 255) / 256, 256>>>(out);
}

// round 4
// speedup vs baseline: 1.7584x; 1.7584x over previous
#include <cuda_runtime.h>
#include <cuda_bf16.h>
#include <cstdint>

// ---------------------------------------------------------------------------
// GraphSAGE on GB300, round 3:
//  - CSR pull-mode mean aggregation (no atomics in the hot path, no zeroing)
//  - tf32 mma.sync GEMMs (tensor pipe) with fused bias/ReLU/dropout epilogue
//  - layer-2 linearity trick: transform to 64-d first, then aggregate 64-d
// ---------------------------------------------------------------------------

constexpr int   NN   = 50000;
constexpr int   EE   = 800000;
constexpr int   D    = 128;
constexpr int   DO   = 64;
constexpr float PDROP = 0.3f;
constexpr float INV_KEEP = 1.0f / 0.7f;

// ---- scratch (static device globals) ----
__device__ __align__(256) float g_agg[NN * D];
__device__ __align__(256) float g_h0 [NN * D];
__device__ __align__(256) float g_h1 [NN * D];
__device__ __align__(256) float g_y  [NN * DO];
__device__ __align__(256) float g_wT [5 * D * D];
__device__ __align__(256) int   g_deg[NN];
__device__ __align__(256) int   g_rowptr[NN + 1];
__device__ __align__(256) int   g_cursor[NN];
__device__ __align__(256) int   g_adj[EE];

// ---------------------------------------------------------------------------
__global__ void prep_weights(const float* __restrict__ wl0, const float* __restrict__ wr0,
                             const float* __restrict__ wl1, const float* __restrict__ wr1,
                             const float* __restrict__ wl2, const float* __restrict__ wr2) {
    int idx = blockIdx.x * blockDim.x + threadIdx.x;
    if (idx >= 5 * D * D) return;
    int seg = idx / (D * D);
    int r   = idx % (D * D);
    int k = r / D, n = r % D;
    float v;
    switch (seg) {
        case 0:  v = wl0[n * D + k]; break;
        case 1:  v = wr0[n * D + k]; break;
        case 2:  v = wl1[n * D + k]; break;
        case 3:  v = wr1[n * D + k]; break;
        default: v = (n < DO) ? wl2[n * D + k] : wr2[(n - DO) * D + k]; break;
    }
    g_wT[idx] = v;
}

__global__ void zero_deg() {
    int i = blockIdx.x * blockDim.x + threadIdx.x;
    if (i < NN) g_deg[i] = 0;
}

__global__ void deg_kernel(const int* __restrict__ ei) {
    int e = blockIdx.x * blockDim.x + threadIdx.x;
    if (e < EE) atomicAdd(&g_deg[ei[EE + e]], 1);
}

// single-block exclusive scan over g_deg -> g_rowptr / g_cursor
__global__ void scan_kernel() {
    constexpr int T = 1024;
    constexpr int CHUNK = (NN + T - 1) / T;   // 49
    __shared__ int partial[T];
    int t = threadIdx.x;
    int beg = t * CHUNK;
    int end = min(beg + CHUNK, NN);
    int s = 0;
    for (int i = beg; i < end; ++i) s += g_deg[i];
    partial[t] = s;
    __syncthreads();
    for (int off = 1; off < T; off <<= 1) {
        int v = 0;
        if (t >= off) v = partial[t - off];
        __syncthreads();
        if (t >= off) partial[t] += v;
        __syncthreads();
    }
    int run = (t > 0) ? partial[t - 1] : 0;
    for (int i = beg; i < end; ++i) {
        g_rowptr[i] = run;
        g_cursor[i] = run;
        run += g_deg[i];
    }
    if (t == T - 1) g_rowptr[NN] = partial[T - 1];
}

__global__ void fill_kernel(const int* __restrict__ ei) {
    int e = blockIdx.x * blockDim.x + threadIdx.x;
    if (e < EE) {
        int d = ei[EE + e];
        int pos = atomicAdd(&g_cursor[d], 1);
        g_adj[pos] = ei[e];
    }
}

// ---------------------------------------------------------------------------
// Pull-mode mean aggregation, 128-d: one warp per node, one float4 per lane.
// ---------------------------------------------------------------------------
__global__ void pull128_kernel(const float4* __restrict__ feat, float4* __restrict__ out) {
    int warp = (blockIdx.x * blockDim.x + threadIdx.x) >> 5;
    int lane = threadIdx.x & 31;
    if (warp >= NN) return;
    int beg = g_rowptr[warp], end = g_rowptr[warp + 1];
    float4 a0 = make_float4(0.f, 0.f, 0.f, 0.f);
    float4 a1 = make_float4(0.f, 0.f, 0.f, 0.f);
    for (int eb = beg; eb < end; eb += 32) {
        int n = end - eb;
        int myAdj = (lane < n) ? __ldg(&g_adj[eb + lane]) : 0;
        int lim = min(n, 32);
        int t = 0;
        for (; t + 2 <= lim; t += 2) {
            int s0 = __shfl_sync(0xffffffffu, myAdj, t);
            int s1 = __shfl_sync(0xffffffffu, myAdj, t + 1);
            float4 v0 = __ldg(&feat[(size_t)s0 * 32 + lane]);
            float4 v1 = __ldg(&feat[(size_t)s1 * 32 + lane]);
            a0.x += v0.x; a0.y += v0.y; a0.z += v0.z; a0.w += v0.w;
            a1.x += v1.x; a1.y += v1.y; a1.z += v1.z; a1.w += v1.w;
        }
        if (t < lim) {
            int s0 = __shfl_sync(0xffffffffu, myAdj, t);
            float4 v0 = __ldg(&feat[(size_t)s0 * 32 + lane]);
            a0.x += v0.x; a0.y += v0.y; a0.z += v0.z; a0.w += v0.w;
        }
    }
    float sc = 1.0f / fmaxf((float)(end - beg), 1.0f);
    a0.x = (a0.x + a1.x) * sc; a0.y = (a0.y + a1.y) * sc;
    a0.z = (a0.z + a1.z) * sc; a0.w = (a0.w + a1.w) * sc;
    out[(size_t)warp * 32 + lane] = a0;
}

// Pull-mode mean, 64-d, accumulating into out (+=). Half-warp per node.
__global__ void pull64_add_kernel(const float4* __restrict__ feat, float4* __restrict__ out) {
    int gid = blockIdx.x * blockDim.x + threadIdx.x;
    int node = gid >> 4;
    int c = gid & 15;
    if (node >= NN) return;
    int beg = g_rowptr[node], end = g_rowptr[node + 1];
    float4 a0 = make_float4(0.f, 0.f, 0.f, 0.f);
    float4 a1 = make_float4(0.f, 0.f, 0.f, 0.f);
    for (int eb = beg; eb < end; eb += 16) {
        int n = end - eb;
        int myAdj = (c < n) ? __ldg(&g_adj[eb + c]) : 0;
        int lim = min(n, 16);
        int t = 0;
        for (; t + 2 <= lim; t += 2) {
            int s0 = __shfl_sync(0xffffffffu, myAdj, t, 16);
            int s1 = __shfl_sync(0xffffffffu, myAdj, t + 1, 16);
            float4 v0 = __ldg(&feat[(size_t)s0 * 16 + c]);
            float4 v1 = __ldg(&feat[(size_t)s1 * 16 + c]);
            a0.x += v0.x; a0.y += v0.y; a0.z += v0.z; a0.w += v0.w;
            a1.x += v1.x; a1.y += v1.y; a1.z += v1.z; a1.w += v1.w;
        }
        if (t < lim) {
            int s0 = __shfl_sync(0xffffffffu, myAdj, t, 16);
            float4 v0 = __ldg(&feat[(size_t)s0 * 16 + c]);
            a0.x += v0.x; a0.y += v0.y; a0.z += v0.z; a0.w += v0.w;
        }
    }
    float sc = 1.0f / fmaxf((float)(end - beg), 1.0f);
    float4 o = out[(size_t)node * 16 + c];
    o.x += (a0.x + a1.x) * sc; o.y += (a0.y + a1.y) * sc;
    o.z += (a0.z + a1.z) * sc; o.w += (a0.w + a1.w) * sc;
    out[(size_t)node * 16 + c] = o;
}

// ---------------------------------------------------------------------------
// tf32 tensor-core GEMM.
// MODE 0: C = relu( mean @ Wl^T + b + h @ Wr^T ) * dropout   (K=256, N=128)
// MODE 1: cols 0..63 -> y = h1 @ wl2^T ; cols 64..127 -> out = h1 @ wr2^T + b
// BM=128, BN=128, BK=32; 8 warps, warp tile 64x32 (mma m16n8k8 tf32).
// ---------------------------------------------------------------------------
__device__ __forceinline__ uint32_t f2tf32(float f) {
    uint32_t r;
    asm("cvt.rna.tf32.f32 %0, %1;" : "=r"(r) : "f"(f));
    return r;
}

template <int MODE>
__launch_bounds__(256)
__global__ void gemm_tf32(const float* __restrict__ A1, const float* __restrict__ A2,
                          const float* __restrict__ WT, const float* __restrict__ bias,
                          const float* __restrict__ u,
                          float* __restrict__ out1, float* __restrict__ out2) {
    constexpr int BM = 128, BN = 128, BK = 32;
    constexpr int KT = (MODE == 0) ? 256 : 128;
    __shared__ uint32_t As[BM][BK + 4];   // row-major A tile (tf32 bits)
    __shared__ uint32_t Ws[BK][BN + 8];   // k-major W tile  (tf32 bits)

    const int tid  = threadIdx.x;
    const int wid  = tid >> 5;
    const int lane = tid & 31;
    const int gidq = lane >> 2;       // 0..7
    const int tg   = lane & 3;        // 0..3
    const int rowBase = (wid >> 2) * 64;   // warp M offset (0 or 64)
    const int colBase = (wid & 3) * 32;    // warp N offset (0,32,64,96)
    const int mBase = blockIdx.x * BM;

    float acc[4][4][4];
    #pragma unroll
    for (int i = 0; i < 4; ++i)
        #pragma unroll
        for (int j = 0; j < 4; ++j)
            #pragma unroll
            for (int r = 0; r < 4; ++r) acc[i][j][r] = 0.f;

    for (int kb = 0; kb < KT; kb += BK) {
        const float* A = A1;
        int ko = kb;
        if constexpr (MODE == 0) {
            if (kb >= 128) { A = A2; ko = kb - 128; }
        }
        // A tile: 128 rows x 32 k -> 1024 float4 loads over 256 threads x 4
        #pragma unroll
        for (int it = 0; it < 4; ++it) {
            int j   = tid + it * 256;        // 0..1023
            int row = j >> 3;                // 0..127
            int kq  = (j & 7) * 4;           // 0..28
            int gr  = mBase + row;
            float4 v = make_float4(0.f, 0.f, 0.f, 0.f);
            if (gr < NN) v = __ldg((const float4*)&A[(size_t)gr * D + ko + kq]);
            uint4 w;
            w.x = f2tf32(v.x); w.y = f2tf32(v.y); w.z = f2tf32(v.z); w.w = f2tf32(v.w);
            *(uint4*)&As[row][kq] = w;
        }
        // W tile: 32 k x 128 n
        #pragma unroll
        for (int it = 0; it < 4; ++it) {
            int j  = tid + it * 256;
            int kr = j >> 5;                 // 0..31
            int nq = (j & 31) * 4;           // 0..124
            float4 v = __ldg((const float4*)&WT[(size_t)(kb + kr) * BN + nq]);
            uint4 w;
            w.x = f2tf32(v.x); w.y = f2tf32(v.y); w.z = f2tf32(v.z); w.w = f2tf32(v.w);
            *(uint4*)&Ws[kr][nq] = w;
        }
        __syncthreads();

        #pragma unroll
        for (int ks = 0; ks < BK / 8; ++ks) {
            uint32_t a[4][4], b[4][2];
            #pragma unroll
            for (int i = 0; i < 4; ++i) {
                int m = rowBase + i * 16 + gidq;
                int k = ks * 8 + tg;
                a[i][0] = As[m][k];
                a[i][1] = As[m + 8][k];
                a[i][2] = As[m][k + 4];
                a[i][3] = As[m + 8][k + 4];
            }
            #pragma unroll
            for (int j = 0; j < 4; ++j) {
                int n = colBase + j * 8 + gidq;
                int k = ks * 8 + tg;
                b[j][0] = Ws[k][n];
                b[j][1] = Ws[k + 4][n];
            }
            #pragma unroll
            for (int i = 0; i < 4; ++i)
                #pragma unroll
                for (int j = 0; j < 4; ++j)
                    asm volatile(
                        "mma.sync.aligned.m16n8k8.row.col.f32.tf32.tf32.f32 "
                        "{%0,%1,%2,%3}, {%4,%5,%6,%7}, {%8,%9}, {%0,%1,%2,%3};"
                        : "+f"(acc[i][j][0]), "+f"(acc[i][j][1]),
                          "+f"(acc[i][j][2]), "+f"(acc[i][j][3])
                        : "r"(a[i][0]), "r"(a[i][1]), "r"(a[i][2]), "r"(a[i][3]),
                          "r"(b[j][0]), "r"(b[j][1]));
        }
        __syncthreads();
    }

    // ---- epilogue ----
    if constexpr (MODE == 0) {
        float2 bs[4];
        #pragma unroll
        for (int j = 0; j < 4; ++j) {
            int col = colBase + j * 8 + 2 * tg;
            bs[j].x = __ldg(&bias[col]);
            bs[j].y = __ldg(&bias[col + 1]);
        }
        #pragma unroll
        for (int i = 0; i < 4; ++i) {
            #pragma unroll
            for (int half = 0; half < 2; ++half) {
                int r = mBase + rowBase + i * 16 + gidq + half * 8;
                if (r >= NN) continue;
                #pragma unroll
                for (int j = 0; j < 4; ++j) {
                    int col = colBase + j * 8 + 2 * tg;
                    float c0 = acc[i][j][half * 2 + 0];
                    float c1 = acc[i][j][half * 2 + 1];
                    float2 uu = *(const float2*)&u[(size_t)r * D + col];
                    float2 o;
                    o.x = fmaxf(c0 + bs[j].x, 0.f) * ((uu.x >= PDROP) ? INV_KEEP : 0.f);
                    o.y = fmaxf(c1 + bs[j].y, 0.f) * ((uu.y >= PDROP) ? INV_KEEP : 0.f);
                    *(float2*)&out1[(size_t)r * D + col] = o;
                }
            }
        }
    } else {
        const bool isY = (colBase < 64);
        float2 bs[4];
        #pragma unroll
        for (int j = 0; j < 4; ++j) {
            if (!isY) {
                int col = colBase - 64 + j * 8 + 2 * tg;
                bs[j].x = __ldg(&bias[col]);
                bs[j].y = __ldg(&bias[col + 1]);
            } else {
                bs[j].x = bs[j].y = 0.f;
            }
        }
        #pragma unroll
        for (int i = 0; i < 4; ++i) {
            #pragma unroll
            for (int half = 0; half < 2; ++half) {
                int r = mBase + rowBase + i * 16 + gidq + half * 8;
                if (r >= NN) continue;
                #pragma unroll
                for (int j = 0; j < 4; ++j) {
                    float c0 = acc[i][j][half * 2 + 0];
                    float c1 = acc[i][j][half * 2 + 1];
                    if (isY) {
                        int col = colBase + j * 8 + 2 * tg;
                        float2 o = make_float2(c0, c1);
                        *(float2*)&out1[(size_t)r * DO + col] = o;
                    } else {
                        int col = colBase - 64 + j * 8 + 2 * tg;
                        float2 o = make_float2(c0 + bs[j].x, c1 + bs[j].y);
                        *(float2*)&out2[(size_t)r * DO + col] = o;
                    }
                }
            }
        }
    }
}

// ---------------------------------------------------------------------------
extern "C" void kernel_launch(void* const* d_in, const int* in_sizes, int n_in,
                              void* d_out, int out_size) {
    const float* x   = (const float*)d_in[0];
    const float* u1  = (const float*)d_in[1];
    const float* u2  = (const float*)d_in[2];
    const float* wl0 = (const float*)d_in[3];
    const float* bl0 = (const float*)d_in[4];
    const float* wr0 = (const float*)d_in[5];
    const float* wl1 = (const float*)d_in[6];
    const float* bl1 = (const float*)d_in[7];
    const float* wr1 = (const float*)d_in[8];
    const float* wl2 = (const float*)d_in[9];
    const float* bl2 = (const float*)d_in[10];
    const float* wr2 = (const float*)d_in[11];
    const int*   ei  = (const int*)d_in[12];
    float* out = (float*)d_out;

    float *agg, *h0, *h1, *y, *wT;
    cudaGetSymbolAddress((void**)&agg, g_agg);
    cudaGetSymbolAddress((void**)&h0,  g_h0);
    cudaGetSymbolAddress((void**)&h1,  g_h1);
    cudaGetSymbolAddress((void**)&y,   g_y);
    cudaGetSymbolAddress((void**)&wT,  g_wT);

    const int gemmBlocks = (NN + 127) / 128;   // 391

    // prep: weight transposes + CSR build
    prep_weights<<<(5 * D * D + 255) / 256, 256>>>(wl0, wr0, wl1, wr1, wl2, wr2);
    zero_deg<<<(NN + 255) / 256, 256>>>();
    deg_kernel<<<EE / 256, 256>>>(ei);
    scan_kernel<<<1, 1024>>>();
    fill_kernel<<<EE / 256, 256>>>(ei);

    // layer 0
    pull128_kernel<<<(NN * 32) / 256, 256>>>((const float4*)x, (float4*)agg);
    gemm_tf32<0><<<gemmBlocks, 256>>>(agg, x, wT, bl0, u1, h0, nullptr);

    // layer 1
    pull128_kernel<<<(NN * 32) / 256, 256>>>((const float4*)h0, (float4*)agg);
    gemm_tf32<0><<<gemmBlocks, 256>>>(agg, h0, wT + 2 * D * D, bl1, u2, h1, nullptr);

    // layer 2: transform first (y + residual), then 64-d pull-add into out
    gemm_tf32<1><<<gemmBlocks, 256>>>(h1, nullptr, wT + 4 * D * D, bl2, nullptr, y, out);
    pull64_add_kernel<<<(NN * 16) / 256, 256>>>((const float4*)y, (float4*)out);
}

// round 7
// speedup vs baseline: 2.3151x; 1.3166x over previous
#include <cuda_runtime.h>
#include <cuda_bf16.h>
#include <cstdint>

// ---------------------------------------------------------------------------
// GraphSAGE on GB300, round 4:
//  - CSR pull-mode mean aggregation (no atomics in hot path)
//  - tf32 mma.sync GEMMs with fused bias/ReLU/dropout epilogue
//  - layer-2 linearity trick (transform to 64-d, then aggregate)
//  - NEW: multi-block CSR scan (was 78 us on a single block -> ~6 us)
// ---------------------------------------------------------------------------

constexpr int   NN   = 50000;
constexpr int   EE   = 800000;
constexpr int   D    = 128;
constexpr int   DO   = 64;
constexpr float PDROP = 0.3f;
constexpr float INV_KEEP = 1.0f / 0.7f;

constexpr int SCAN_B = 256;                       // elements per scan block
constexpr int SCAN_NBLK = (NN + SCAN_B - 1) / SCAN_B;   // 196

// ---- scratch (static device globals) ----
__device__ __align__(256) float g_agg[NN * D];
__device__ __align__(256) float g_h0 [NN * D];
__device__ __align__(256) float g_h1 [NN * D];
__device__ __align__(256) float g_y  [NN * DO];
__device__ __align__(256) float g_wT [5 * D * D];
__device__ __align__(256) int   g_deg[NN];
__device__ __align__(256) int   g_rowptr[NN + 1];
__device__ __align__(256) int   g_cursor[NN];
__device__ __align__(256) int   g_adj[EE];
__device__ __align__(256) int   g_blksum[SCAN_NBLK + 1];

// ---------------------------------------------------------------------------
// prep: weight transposes (coalesced [k][n] layout) + zero degree counters
// ---------------------------------------------------------------------------
__global__ void prep_weights(const float* __restrict__ wl0, const float* __restrict__ wr0,
                             const float* __restrict__ wl1, const float* __restrict__ wr1,
                             const float* __restrict__ wl2, const float* __restrict__ wr2) {
    int idx = blockIdx.x * blockDim.x + threadIdx.x;
    if (idx < NN) g_deg[idx] = 0;
    if (idx >= 5 * D * D) return;
    int seg = idx / (D * D);
    int r   = idx % (D * D);
    int k = r / D, n = r % D;
    float v;
    switch (seg) {
        case 0:  v = wl0[n * D + k]; break;
        case 1:  v = wr0[n * D + k]; break;
        case 2:  v = wl1[n * D + k]; break;
        case 3:  v = wr1[n * D + k]; break;
        default: v = (n < DO) ? wl2[n * D + k] : wr2[(n - DO) * D + k]; break;
    }
    g_wT[idx] = v;
}

__global__ void deg_kernel(const int* __restrict__ ei) {
    int e = blockIdx.x * blockDim.x + threadIdx.x;
    if (e < EE) atomicAdd(&g_deg[ei[EE + e]], 1);
}

// ---- multi-block exclusive scan: s1 (block reduce) -> s2 (scan sums) -> s3 ----
__global__ void scan_s1() {
    __shared__ int sh[SCAN_B];
    int idx = blockIdx.x * SCAN_B + threadIdx.x;
    int v = (idx < NN) ? g_deg[idx] : 0;
    sh[threadIdx.x] = v;
    __syncthreads();
    for (int off = SCAN_B / 2; off > 0; off >>= 1) {
        if (threadIdx.x < off) sh[threadIdx.x] += sh[threadIdx.x + off];
        __syncthreads();
    }
    if (threadIdx.x == 0) g_blksum[blockIdx.x] = sh[0];
}

__global__ void scan_s2() {
    __shared__ int sh[SCAN_NBLK];
    int t = threadIdx.x;
    if (t < SCAN_NBLK) sh[t] = g_blksum[t];
    __syncthreads();
    // Hillis-Steele inclusive scan over SCAN_NBLK elements
    for (int off = 1; off < SCAN_NBLK; off <<= 1) {
        int v = 0;
        if (t < SCAN_NBLK && t >= off) v = sh[t - off];
        __syncthreads();
        if (t < SCAN_NBLK && t >= off) sh[t] += v;
        __syncthreads();
    }
    if (t < SCAN_NBLK) g_blksum[t] = (t > 0) ? sh[t - 1] : 0;   // exclusive
    if (t == SCAN_NBLK - 1) {
        g_blksum[SCAN_NBLK] = sh[SCAN_NBLK - 1];                 // total
        g_rowptr[NN] = sh[SCAN_NBLK - 1];
    }
}

__global__ void scan_s3() {
    __shared__ int sh[SCAN_B];
    int idx = blockIdx.x * SCAN_B + threadIdx.x;
    int t = threadIdx.x;
    int v = (idx < NN) ? g_deg[idx] : 0;
    sh[t] = v;
    __syncthreads();
    for (int off = 1; off < SCAN_B; off <<= 1) {
        int p = 0;
        if (t >= off) p = sh[t - off];
        __syncthreads();
        if (t >= off) sh[t] += p;
        __syncthreads();
    }
    if (idx < NN) {
        int ex = sh[t] - v + g_blksum[blockIdx.x];   // exclusive prefix
        g_rowptr[idx] = ex;
        g_cursor[idx] = ex;
    }
}

__global__ void fill_kernel(const int* __restrict__ ei) {
    int e = blockIdx.x * blockDim.x + threadIdx.x;
    if (e < EE) {
        int d = ei[EE + e];
        int pos = atomicAdd(&g_cursor[d], 1);
        g_adj[pos] = ei[e];
    }
}

// ---------------------------------------------------------------------------
// Pull-mode mean aggregation, 128-d: one warp per node, one float4 per lane.
// ---------------------------------------------------------------------------
__global__ void pull128_kernel(const float4* __restrict__ feat, float4* __restrict__ out) {
    int warp = (blockIdx.x * blockDim.x + threadIdx.x) >> 5;
    int lane = threadIdx.x & 31;
    if (warp >= NN) return;
    int beg = g_rowptr[warp], end = g_rowptr[warp + 1];
    float4 a0 = make_float4(0.f, 0.f, 0.f, 0.f);
    float4 a1 = make_float4(0.f, 0.f, 0.f, 0.f);
    for (int eb = beg; eb < end; eb += 32) {
        int n = end - eb;
        int myAdj = (lane < n) ? __ldg(&g_adj[eb + lane]) : 0;
        int lim = min(n, 32);
        int t = 0;
        for (; t + 2 <= lim; t += 2) {
            int s0 = __shfl_sync(0xffffffffu, myAdj, t);
            int s1 = __shfl_sync(0xffffffffu, myAdj, t + 1);
            float4 v0 = __ldg(&feat[(size_t)s0 * 32 + lane]);
            float4 v1 = __ldg(&feat[(size_t)s1 * 32 + lane]);
            a0.x += v0.x; a0.y += v0.y; a0.z += v0.z; a0.w += v0.w;
            a1.x += v1.x; a1.y += v1.y; a1.z += v1.z; a1.w += v1.w;
        }
        if (t < lim) {
            int s0 = __shfl_sync(0xffffffffu, myAdj, t);
            float4 v0 = __ldg(&feat[(size_t)s0 * 32 + lane]);
            a0.x += v0.x; a0.y += v0.y; a0.z += v0.z; a0.w += v0.w;
        }
    }
    float sc = 1.0f / fmaxf((float)(end - beg), 1.0f);
    a0.x = (a0.x + a1.x) * sc; a0.y = (a0.y + a1.y) * sc;
    a0.z = (a0.z + a1.z) * sc; a0.w = (a0.w + a1.w) * sc;
    out[(size_t)warp * 32 + lane] = a0;
}

// Pull-mode mean, 64-d, accumulating into out (+=). Half-warp per node.
__global__ void pull64_add_kernel(const float4* __restrict__ feat, float4* __restrict__ out) {
    int gid = blockIdx.x * blockDim.x + threadIdx.x;
    int node = gid >> 4;
    int c = gid & 15;
    if (node >= NN) return;
    int beg = g_rowptr[node], end = g_rowptr[node + 1];
    float4 a0 = make_float4(0.f, 0.f, 0.f, 0.f);
    float4 a1 = make_float4(0.f, 0.f, 0.f, 0.f);
    for (int eb = beg; eb < end; eb += 16) {
        int n = end - eb;
        int myAdj = (c < n) ? __ldg(&g_adj[eb + c]) : 0;
        int lim = min(n, 16);
        int t = 0;
        for (; t + 2 <= lim; t += 2) {
            int s0 = __shfl_sync(0xffffffffu, myAdj, t, 16);
            int s1 = __shfl_sync(0xffffffffu, myAdj, t + 1, 16);
            float4 v0 = __ldg(&feat[(size_t)s0 * 16 + c]);
            float4 v1 = __ldg(&feat[(size_t)s1 * 16 + c]);
            a0.x += v0.x; a0.y += v0.y; a0.z += v0.z; a0.w += v0.w;
            a1.x += v1.x; a1.y += v1.y; a1.z += v1.z; a1.w += v1.w;
        }
        if (t < lim) {
            int s0 = __shfl_sync(0xffffffffu, myAdj, t, 16);
            float4 v0 = __ldg(&feat[(size_t)s0 * 16 + c]);
            a0.x += v0.x; a0.y += v0.y; a0.z += v0.z; a0.w += v0.w;
        }
    }
    float sc = 1.0f / fmaxf((float)(end - beg), 1.0f);
    float4 o = out[(size_t)node * 16 + c];
    o.x += (a0.x + a1.x) * sc; o.y += (a0.y + a1.y) * sc;
    o.z += (a0.z + a1.z) * sc; o.w += (a0.w + a1.w) * sc;
    out[(size_t)node * 16 + c] = o;
}

// ---------------------------------------------------------------------------
// tf32 tensor-core GEMM (same as round 3).
// MODE 0: C = relu( mean @ Wl^T + b + h @ Wr^T ) * dropout   (K=256, N=128)
// MODE 1: cols 0..63 -> y = h1 @ wl2^T ; cols 64..127 -> out = h1 @ wr2^T + b
// ---------------------------------------------------------------------------
__device__ __forceinline__ uint32_t f2tf32(float f) {
    uint32_t r;
    asm("cvt.rna.tf32.f32 %0, %1;" : "=r"(r) : "f"(f));
    return r;
}

template <int MODE>
__launch_bounds__(256)
__global__ void gemm_tf32(const float* __restrict__ A1, const float* __restrict__ A2,
                          const float* __restrict__ WT, const float* __restrict__ bias,
                          const float* __restrict__ u,
                          float* __restrict__ out1, float* __restrict__ out2) {
    constexpr int BM = 128, BN = 128, BK = 32;
    constexpr int KT = (MODE == 0) ? 256 : 128;
    __shared__ uint32_t As[BM][BK + 4];
    __shared__ uint32_t Ws[BK][BN + 8];

    const int tid  = threadIdx.x;
    const int wid  = tid >> 5;
    const int lane = tid & 31;
    const int gidq = lane >> 2;
    const int tg   = lane & 3;
    const int rowBase = (wid >> 2) * 64;
    const int colBase = (wid & 3) * 32;
    const int mBase = blockIdx.x * BM;

    float acc[4][4][4];
    #pragma unroll
    for (int i = 0; i < 4; ++i)
        #pragma unroll
        for (int j = 0; j < 4; ++j)
            #pragma unroll
            for (int r = 0; r < 4; ++r) acc[i][j][r] = 0.f;

    for (int kb = 0; kb < KT; kb += BK) {
        const float* A = A1;
        int ko = kb;
        if constexpr (MODE == 0) {
            if (kb >= 128) { A = A2; ko = kb - 128; }
        }
        #pragma unroll
        for (int it = 0; it < 4; ++it) {
            int j   = tid + it * 256;
            int row = j >> 3;
            int kq  = (j & 7) * 4;
            int gr  = mBase + row;
            float4 v = make_float4(0.f, 0.f, 0.f, 0.f);
            if (gr < NN) v = __ldg((const float4*)&A[(size_t)gr * D + ko + kq]);
            uint4 w;
            w.x = f2tf32(v.x); w.y = f2tf32(v.y); w.z = f2tf32(v.z); w.w = f2tf32(v.w);
            *(uint4*)&As[row][kq] = w;
        }
        #pragma unroll
        for (int it = 0; it < 4; ++it) {
            int j  = tid + it * 256;
            int kr = j >> 5;
            int nq = (j & 31) * 4;
            float4 v = __ldg((const float4*)&WT[(size_t)(kb + kr) * BN + nq]);
            uint4 w;
            w.x = f2tf32(v.x); w.y = f2tf32(v.y); w.z = f2tf32(v.z); w.w = f2tf32(v.w);
            *(uint4*)&Ws[kr][nq] = w;
        }
        __syncthreads();

        #pragma unroll
        for (int ks = 0; ks < BK / 8; ++ks) {
            uint32_t a[4][4], b[4][2];
            #pragma unroll
            for (int i = 0; i < 4; ++i) {
                int m = rowBase + i * 16 + gidq;
                int k = ks * 8 + tg;
                a[i][0] = As[m][k];
                a[i][1] = As[m + 8][k];
                a[i][2] = As[m][k + 4];
                a[i][3] = As[m + 8][k + 4];
            }
            #pragma unroll
            for (int j = 0; j < 4; ++j) {
                int n = colBase + j * 8 + gidq;
                int k = ks * 8 + tg;
                b[j][0] = Ws[k][n];
                b[j][1] = Ws[k + 4][n];
            }
            #pragma unroll
            for (int i = 0; i < 4; ++i)
                #pragma unroll
                for (int j = 0; j < 4; ++j)
                    asm volatile(
                        "mma.sync.aligned.m16n8k8.row.col.f32.tf32.tf32.f32 "
                        "{%0,%1,%2,%3}, {%4,%5,%6,%7}, {%8,%9}, {%0,%1,%2,%3};"
                        : "+f"(acc[i][j][0]), "+f"(acc[i][j][1]),
                          "+f"(acc[i][j][2]), "+f"(acc[i][j][3])
                        : "r"(a[i][0]), "r"(a[i][1]), "r"(a[i][2]), "r"(a[i][3]),
                          "r"(b[j][0]), "r"(b[j][1]));
        }
        __syncthreads();
    }

    if constexpr (MODE == 0) {
        float2 bs[4];
        #pragma unroll
        for (int j = 0; j < 4; ++j) {
            int col = colBase + j * 8 + 2 * tg;
            bs[j].x = __ldg(&bias[col]);
            bs[j].y = __ldg(&bias[col + 1]);
        }
        #pragma unroll
        for (int i = 0; i < 4; ++i) {
            #pragma unroll
            for (int half = 0; half < 2; ++half) {
                int r = mBase + rowBase + i * 16 + gidq + half * 8;
                if (r >= NN) continue;
                #pragma unroll
                for (int j = 0; j < 4; ++j) {
                    int col = colBase + j * 8 + 2 * tg;
                    float c0 = acc[i][j][half * 2 + 0];
                    float c1 = acc[i][j][half * 2 + 1];
                    float2 uu = *(const float2*)&u[(size_t)r * D + col];
                    float2 o;
                    o.x = fmaxf(c0 + bs[j].x, 0.f) * ((uu.x >= PDROP) ? INV_KEEP : 0.f);
                    o.y = fmaxf(c1 + bs[j].y, 0.f) * ((uu.y >= PDROP) ? INV_KEEP : 0.f);
                    *(float2*)&out1[(size_t)r * D + col] = o;
                }
            }
        }
    } else {
        const bool isY = (colBase < 64);
        float2 bs[4];
        #pragma unroll
        for (int j = 0; j < 4; ++j) {
            if (!isY) {
                int col = colBase - 64 + j * 8 + 2 * tg;
                bs[j].x = __ldg(&bias[col]);
                bs[j].y = __ldg(&bias[col + 1]);
            } else {
                bs[j].x = bs[j].y = 0.f;
            }
        }
        #pragma unroll
        for (int i = 0; i < 4; ++i) {
            #pragma unroll
            for (int half = 0; half < 2; ++half) {
                int r = mBase + rowBase + i * 16 + gidq + half * 8;
                if (r >= NN) continue;
                #pragma unroll
                for (int j = 0; j < 4; ++j) {
                    float c0 = acc[i][j][half * 2 + 0];
                    float c1 = acc[i][j][half * 2 + 1];
                    if (isY) {
                        int col = colBase + j * 8 + 2 * tg;
                        *(float2*)&out1[(size_t)r * DO + col] = make_float2(c0, c1);
                    } else {
                        int col = colBase - 64 + j * 8 + 2 * tg;
                        *(float2*)&out2[(size_t)r * DO + col] =
                            make_float2(c0 + bs[j].x, c1 + bs[j].y);
                    }
                }
            }
        }
    }
}

// ---------------------------------------------------------------------------
extern "C" void kernel_launch(void* const* d_in, const int* in_sizes, int n_in,
                              void* d_out, int out_size) {
    const float* x   = (const float*)d_in[0];
    const float* u1  = (const float*)d_in[1];
    const float* u2  = (const float*)d_in[2];
    const float* wl0 = (const float*)d_in[3];
    const float* bl0 = (const float*)d_in[4];
    const float* wr0 = (const float*)d_in[5];
    const float* wl1 = (const float*)d_in[6];
    const float* bl1 = (const float*)d_in[7];
    const float* wr1 = (const float*)d_in[8];
    const float* wl2 = (const float*)d_in[9];
    const float* bl2 = (const float*)d_in[10];
    const float* wr2 = (const float*)d_in[11];
    const int*   ei  = (const int*)d_in[12];
    float* out = (float*)d_out;

    float *agg, *h0, *h1, *y, *wT;
    cudaGetSymbolAddress((void**)&agg, g_agg);
    cudaGetSymbolAddress((void**)&h0,  g_h0);
    cudaGetSymbolAddress((void**)&h1,  g_h1);
    cudaGetSymbolAddress((void**)&y,   g_y);
    cudaGetSymbolAddress((void**)&wT,  g_wT);

    const int gemmBlocks = (NN + 127) / 128;   // 391

    // prep: weight transposes + zero deg, then CSR build (multi-block scan)
    prep_weights<<<(5 * D * D + 255) / 256, 256>>>(wl0, wr0, wl1, wr1, wl2, wr2);
    deg_kernel<<<EE / 256, 256>>>(ei);
    scan_s1<<<SCAN_NBLK, SCAN_B>>>();
    scan_s2<<<1, 256>>>();
    scan_s3<<<SCAN_NBLK, SCAN_B>>>();
    fill_kernel<<<EE / 256, 256>>>(ei);

    // layer 0
    pull128_kernel<<<(NN * 32) / 256, 256>>>((const float4*)x, (float4*)agg);
    gemm_tf32<0><<<gemmBlocks, 256>>>(agg, x, wT, bl0, u1, h0, nullptr);

    // layer 1
    pull128_kernel<<<(NN * 32) / 256, 256>>>((const float4*)h0, (float4*)agg);
    gemm_tf32<0><<<gemmBlocks, 256>>>(agg, h0, wT + 2 * D * D, bl1, u2, h1, nullptr);

    // layer 2: transform first (y + residual), then 64-d pull-add into out
    gemm_tf32<1><<<gemmBlocks, 256>>>(h1, nullptr, wT + 4 * D * D, bl2, nullptr, y, out);
    pull64_add_kernel<<<(NN * 16) / 256, 256>>>((const float4*)y, (float4*)out);
}